// round 9
// baseline (speedup 1.0000x reference)
#include <cuda_runtime.h>

#define N_SAMP 8000
#define T_DIM  64
#define F_DIM  64
#define NCOL   320   // 40 time steps * 8 features
#define W127   91440 // 127*144*5
#define NBIN   8192

// 10.24 MB scratch for ranks: layout [n][t*8+e]
__device__ float g_rank[(size_t)N_SAMP * NCOL];

__device__ __forceinline__ unsigned desc_key(float v){
    unsigned b = __float_as_uint(v);
    unsigned u = b ^ ((b & 0x80000000u) ? 0xFFFFFFFFu : 0x80000000u); // ascending order key
    return ~u;                                                        // descending order key
}

// ---------------------------------------------------------------------------
// Kernel 1: exact descending rank (stable, index tie-break) per (t,e) column
// over all 8000 samples. One block per column, 1024 threads.
// Single atomic pass: atomicAdd returns within-bin position; scatter is a
// plain store after the scan. 8192 bins.
// Shared: du[8192] u32 | hist[8192] u32 | order[8192] u16  = 81920 B
//   -> 2 blocks/SM (thread-cap), 320 blocks ~ 1 wave.
// ---------------------------------------------------------------------------
__global__ __launch_bounds__(1024) void rank_kernel(const float* __restrict__ x){
    extern __shared__ char sm[];
    unsigned*       du    = (unsigned*)sm;                  // 8192 u32
    unsigned*       hist  = du + 8192;                      // 8192 u32
    unsigned short* order = (unsigned short*)(hist + NBIN); // 8192 u16
    __shared__ unsigned wsum[32];

    const int col = blockIdx.x;
    const int tt  = col >> 3;
    const int e   = col & 7;
    const int tid = threadIdx.x;
    const float* xp = x + (size_t)(24 + tt) * F_DIM + e;

    unsigned key[8];
    unsigned pb[8];

    #pragma unroll
    for (int k = 0; k < 8; k++){
        int i = tid + k * 1024;
        unsigned d = 0xFFFFFFFFu;                           // padding sorts last
        if (i < N_SAMP) d = desc_key(__ldg(xp + (size_t)i * (T_DIM * F_DIM)));
        key[k] = d;
        du[i]  = d;
    }
    #pragma unroll
    for (int j = 0; j < NBIN/1024; j++) hist[tid + j * 1024] = 0u;
    __syncthreads();

    // single atomic pass: count AND capture within-bin position
    #pragma unroll
    for (int k = 0; k < 8; k++){
        unsigned b = key[k] >> 19;                          // top 13 bits
        unsigned p = atomicAdd(&hist[b], 1u);
        pb[k] = (b << 13) | p;                              // 13+13 bits
    }
    __syncthreads();

    // exclusive scan over 8192 bins: each thread owns 8 consecutive bins
    unsigned local[8];
    unsigned s = 0;
    const int b0 = tid * 8;
    #pragma unroll
    for (int j = 0; j < 8; j++){ local[j] = hist[b0 + j]; s += local[j]; }
    const unsigned lane = tid & 31, wid = tid >> 5;
    unsigned inc = s;
    #pragma unroll
    for (int off = 1; off < 32; off <<= 1){
        unsigned o = __shfl_up_sync(0xffffffffu, inc, off);
        if (lane >= off) inc += o;
    }
    if (lane == 31) wsum[wid] = inc;
    __syncthreads();
    if (wid == 0){
        unsigned vv = wsum[lane], ii = vv;
        #pragma unroll
        for (int off = 1; off < 32; off <<= 1){
            unsigned o = __shfl_up_sync(0xffffffffu, ii, off);
            if (lane >= off) ii += o;
        }
        wsum[lane] = ii - vv;                               // exclusive warp prefix
    }
    __syncthreads();
    unsigned run = wsum[wid] + (inc - s);                   // exclusive thread prefix
    #pragma unroll
    for (int j = 0; j < 8; j++){ unsigned c = local[j]; hist[b0 + j] = run; run += c; }
    __syncthreads();

    // scatter with plain stores: position = prefix[bin] + saved within-bin pos
    #pragma unroll
    for (int k = 0; k < 8; k++){
        int i = tid + k * 1024;
        unsigned b = pb[k] >> 13, p = pb[k] & 0x1FFFu;
        order[hist[b] + p] = (unsigned short)i;
    }
    __syncthreads();

    // exact rank: base = #elements in smaller bins, + within-bin count with
    // (value, index) tie-break => matches stable argsort of -x.
    #pragma unroll
    for (int k = 0; k < 8; k++){
        int i = tid + k * 1024;
        if (i < N_SAMP){
            unsigned kk    = key[k];
            unsigned b     = kk >> 19;
            unsigned start = hist[b];
            unsigned end   = (b == NBIN - 1) ? 8192u : hist[b + 1];
            int cnt = 0;
            for (unsigned q = start; q < end; q++){
                int m = order[q];
                unsigned km = du[m];
                cnt += (km < kk) || (km == kk && m < i);
            }
            g_rank[(size_t)i * NCOL + col] = (float)((int)start + cnt) * (1.0f / 8000.0f);
        }
    }
}

// ---------------------------------------------------------------------------
// Kernel 2: fused window-stats + single-channel conv + leaky-relu + linear.
// 320 threads / 8 samples per block: thread = (sample s, time t), every lane
// active in one pass. __launch_bounds__(320,2) -> 2 blocks/SM (20 warps).
// ---------------------------------------------------------------------------
__device__ __forceinline__ void ffma2(unsigned long long &d, unsigned long long a, unsigned long long b){
    asm("fma.rn.f32x2 %0, %1, %2, %0;" : "+l"(d) : "l"(a), "l"(b));
}
__device__ __forceinline__ float2 upk2(unsigned long long v){
    float2 f; asm("mov.b64 {%0, %1}, %2;" : "=f"(f.x), "=f"(f.y) : "l"(v)); return f;
}

__global__ void __launch_bounds__(320, 2) main_kernel(
    const float* __restrict__ x, const float* __restrict__ conv_w,
    const float* __restrict__ conv_b, const float* __restrict__ lin_w,
    const float* __restrict__ lin_b, float* __restrict__ out)
{
    extern __shared__ char sm[];
    float* xrowAll = (float*)sm;              // 8 * 40 * 68 = 21760 floats
    float* xeAll   = xrowAll + 8 * 40 * 68;   // 8 * 64 * 8  = 4096
    float* dAll    = xeAll   + 8 * 64 * 8;    // 8 * 200     = 1600
    float* wTs     = dAll    + 8 * 200;       // 720  (wTs[k*144 + c])
    float* linWs   = wTs + 720;               // 36
    float* miscS   = linWs + 36;              // 2

    const int tid   = threadIdx.x;
    const int nbase = blockIdx.x * 8;

    // transpose the single live conv filter: wTs[k][c] = conv_w[127][c][k]
    for (int idx = tid; idx < 720; idx += 320){
        int k = idx / 144, c = idx - k * 144;
        wTs[idx] = conv_w[W127 + c * 5 + k];
    }
    if (tid < 36) linWs[tid] = lin_w[tid];
    if (tid == 36) miscS[0] = conv_b[127];
    if (tid == 37) miscS[1] = lin_b[0];

    // stage rows 24..63, all 64 channels, 8 samples (coalesced, padded stride 68)
    #pragma unroll
    for (int s8 = 0; s8 < 8; s8++){
        const float* src = x + (size_t)(nbase + s8) * (T_DIM * F_DIM) + 1536;
        float* dst = xrowAll + s8 * 2720;
        #pragma unroll
        for (int it = 0; it < 2; it++){
            int f4  = it * 320 + tid;
            int row = f4 >> 4, cc = (f4 & 15) * 4;
            *(float4*)(dst + row * 68 + cc) = *(const float4*)(src + f4 * 4);
        }
    }
    // stage rows 0..63, first 8 features, 8 samples (for window stats)
    #pragma unroll
    for (int it = 0; it < 4; it++){
        int idx = it * 320 + tid;
        if (idx < 1024){
            int s = idx >> 7, q = idx & 127;
            int row = q >> 1, half = (q & 1) * 4;
            *(float4*)(xeAll + s * 512 + row * 8 + half) =
                *(const float4*)(x + (size_t)(nbase + s) * (T_DIM * F_DIM) + row * 64 + half);
        }
    }
    __syncthreads();

    const int s = tid / 40;                   // 0..7 (sample within block)
    const int t = tid - s * 40;               // 0..39
    const int n = nbase + s;
    const float4* xe4 = (const float4*)(xeAll + s * 512);
    float* dW = dAll + s * 200;

    float dst[5] = {0.f, 0.f, 0.f, 0.f, 0.f};
    auto acc4 = [&](int cb, float v0, float v1, float v2, float v3){
        #pragma unroll
        for (int k = 0; k < 5; k++){
            float4 wv = *(const float4*)(wTs + k * 144 + cb);
            dst[k] = fmaf(v0, wv.x, fmaf(v1, wv.y, fmaf(v2, wv.z, fmaf(v3, wv.w, dst[k]))));
        }
    };

    // ---- 20-window stats (rows 5+t .. 24+t), consumed immediately ----
    {
        float s20[8], q20[8], mx20[8], mn20[8];
        #pragma unroll
        for (int e2 = 0; e2 < 8; e2++){ s20[e2]=0.f; q20[e2]=0.f; mx20[e2]=-3.4e38f; mn20[e2]=3.4e38f; }
        #pragma unroll
        for (int j = 0; j < 20; j++){
            float4 a = xe4[(5 + t + j) * 2];
            float4 b = xe4[(5 + t + j) * 2 + 1];
            float v[8] = {a.x, a.y, a.z, a.w, b.x, b.y, b.z, b.w};
            #pragma unroll
            for (int e2 = 0; e2 < 8; e2++){
                float vv = v[e2];
                s20[e2] += vv;
                q20[e2]  = fmaf(vv, vv, q20[e2]);
                mx20[e2] = fmaxf(mx20[e2], vv);
                mn20[e2] = fminf(mn20[e2], vv);
            }
        }
        float mean20[8], std20[8];
        #pragma unroll
        for (int e2 = 0; e2 < 8; e2++){
            mean20[e2] = s20[e2] * 0.05f;
            std20[e2]  = sqrtf(fmaxf((q20[e2] - s20[e2]*s20[e2]*0.05f) * (1.0f/19.0f), 0.f));
        }
        acc4(104, mean20[0], mean20[1], mean20[2], mean20[3]);
        acc4(108, mean20[4], mean20[5], mean20[6], mean20[7]);
        acc4(112, std20[0], std20[1], std20[2], std20[3]);
        acc4(116, std20[4], std20[5], std20[6], std20[7]);
        acc4(128, mx20[0], mx20[1], mx20[2], mx20[3]);
        acc4(132, mx20[4], mx20[5], mx20[6], mx20[7]);
        acc4(136, mn20[0], mn20[1], mn20[2], mn20[3]);
        acc4(140, mn20[4], mn20[5], mn20[6], mn20[7]);
    }
    // ---- 5-window stats (rows 20+t .. 24+t), consumed immediately ----
    {
        float s5[8], q5[8], mx5[8], mn5[8];
        #pragma unroll
        for (int e2 = 0; e2 < 8; e2++){ s5[e2]=0.f; q5[e2]=0.f; mx5[e2]=-3.4e38f; mn5[e2]=3.4e38f; }
        #pragma unroll
        for (int j = 0; j < 5; j++){
            float4 a = xe4[(20 + t + j) * 2];
            float4 b = xe4[(20 + t + j) * 2 + 1];
            float v[8] = {a.x, a.y, a.z, a.w, b.x, b.y, b.z, b.w};
            #pragma unroll
            for (int e2 = 0; e2 < 8; e2++){
                float vv = v[e2];
                s5[e2] += vv;
                q5[e2]  = fmaf(vv, vv, q5[e2]);
                mx5[e2] = fmaxf(mx5[e2], vv);
                mn5[e2] = fminf(mn5[e2], vv);
            }
        }
        float mean5[8], std5[8];
        #pragma unroll
        for (int e2 = 0; e2 < 8; e2++){
            mean5[e2] = s5[e2] * 0.2f;
            std5[e2]  = sqrtf(fmaxf((q5[e2] - s5[e2]*s5[e2]*0.2f) * 0.25f, 0.f));
        }
        acc4( 64, mean5[0], mean5[1], mean5[2], mean5[3]);
        acc4( 68, mean5[4], mean5[5], mean5[6], mean5[7]);
        acc4( 72, std5[0], std5[1], std5[2], std5[3]);
        acc4( 76, std5[4], std5[5], std5[6], std5[7]);
        acc4( 88, mx5[0], mx5[1], mx5[2], mx5[3]);
        acc4( 92, mx5[4], mx5[5], mx5[6], mx5[7]);
        acc4( 96, mn5[0], mn5[1], mn5[2], mn5[3]);
        acc4(100, mn5[4], mn5[5], mn5[6], mn5[7]);
    }
    // ---- ranks (identical for week & month channel groups) ----
    {
        const float4* rp = (const float4*)(g_rank + (size_t)n * NCOL + t * 8);
        float4 rka = rp[0], rkb = rp[1];
        acc4( 80, rka.x, rka.y, rka.z, rka.w);
        acc4( 84, rkb.x, rkb.y, rkb.z, rkb.w);
        acc4(120, rka.x, rka.y, rka.z, rka.w);
        acc4(124, rkb.x, rkb.y, rkb.z, rkb.w);
    }
    // ---- raw 64-channel dot via packed f32x2 FMA ----
    {
        unsigned long long dax[5], day[5];
        #pragma unroll
        for (int k = 0; k < 5; k++){ dax[k] = 0ULL; day[k] = 0ULL; }
        const ulonglong2* xr2 = (const ulonglong2*)(xrowAll + s * 2720 + t * 68);
        #pragma unroll
        for (int c4 = 0; c4 < 16; c4++){
            ulonglong2 xv = xr2[c4];
            #pragma unroll
            for (int k = 0; k < 5; k++){
                ulonglong2 wv = *(const ulonglong2*)(wTs + k * 144 + c4 * 4);
                ffma2(dax[k], xv.x, wv.x);
                ffma2(day[k], xv.y, wv.y);
            }
        }
        #pragma unroll
        for (int k = 0; k < 5; k++){
            float2 a1 = upk2(dax[k]), a2 = upk2(day[k]);
            dW[t * 5 + k] = dst[k] + ((a1.x + a1.y) + (a2.x + a2.y));
        }
    }
    __syncthreads();

    // conv taps across t + bias + leaky relu + linear head: warp per sample.
    // 36 positions on 32 lanes: lane p handles position p; lanes 0..3 also
    // handle positions 32..35.
    const int lane = tid & 31, w = tid >> 5;
    if (w < 8){
        const float* dWw = dAll + w * 200;
        const float convB = miscS[0], linB = miscS[1];
        float h = convB;
        #pragma unroll
        for (int k = 0; k < 5; k++) h += dWw[(lane + k) * 5 + k];
        h = (h >= 0.f) ? h : 0.01f * h;
        float c = h * linWs[lane];
        if (lane < 4){
            float h2 = convB;
            #pragma unroll
            for (int k = 0; k < 5; k++) h2 += dWw[(lane + 32 + k) * 5 + k];
            h2 = (h2 >= 0.f) ? h2 : 0.01f * h2;
            c = fmaf(h2, linWs[lane + 32], c);
        }
        #pragma unroll
        for (int off = 16; off; off >>= 1) c += __shfl_down_sync(0xffffffffu, c, off);
        if (lane == 0) out[nbase + w] = c + linB;
    }
}

// ---------------------------------------------------------------------------
extern "C" void kernel_launch(void* const* d_in, const int* in_sizes, int n_in,
                              void* d_out, int out_size)
{
    const float* x      = (const float*)d_in[0];
    const float* conv_w = (const float*)d_in[1];
    const float* conv_b = (const float*)d_in[2];
    const float* lin_w  = (const float*)d_in[3];
    const float* lin_b  = (const float*)d_in[4];
    float* out = (float*)d_out;

    cudaFuncSetAttribute(rank_kernel, cudaFuncAttributeMaxDynamicSharedMemorySize, 81920);
    cudaFuncSetAttribute(main_kernel, cudaFuncAttributeMaxDynamicSharedMemorySize, 112896);

    rank_kernel<<<NCOL, 1024, 81920>>>(x);
    main_kernel<<<N_SAMP / 8, 320, 112896>>>(x, conv_w, conv_b, lin_w, lin_b, out);
}

// round 14
// speedup vs baseline: 2.3726x; 2.3726x over previous
#include <cuda_runtime.h>

#define N_SAMP 8000
#define T_DIM  64
#define F_DIM  64
#define NCOL   320   // 40 time steps * 8 features
#define W127   91440 // 127*144*5
#define NBIN   4096

// 10.24 MB scratch for ranks: layout [n][t*8+e]
__device__ float g_rank[(size_t)N_SAMP * NCOL];

__device__ __forceinline__ unsigned desc_key(float v){
    unsigned b = __float_as_uint(v);
    unsigned u = b ^ ((b & 0x80000000u) ? 0xFFFFFFFFu : 0x80000000u); // ascending order key
    return ~u;                                                        // descending order key
}

// value-based bin, monotone non-decreasing along descending order.
// bin width 1/512 over [-4,4]: ~uniform occupancy for N(0,1) data.
__device__ __forceinline__ int bin_of_val(float v){
    int t = (int)floorf(v * 512.f) + 2048;
    t = min(max(t, 0), NBIN - 1);
    return (NBIN - 1) - t;
}
// recover original float from descending key
__device__ __forceinline__ float val_of_key(unsigned kk){
    unsigned u = ~kk;
    unsigned b = (u & 0x80000000u) ? (u ^ 0x80000000u) : ~u;
    return __uint_as_float(b);
}

// ---------------------------------------------------------------------------
// Kernel 1: exact descending rank (stable, index tie-break) per (t,e) column
// over all 8000 samples. One block per column, 512 threads, 16 elems/thread.
// Value-based bins keep refinement ~5 elements/bin.
// Shared: du[8192] u32 | hist[4096] u32 | order[8192] u16 = 65536 B
//   -> 3 blocks/SM, 320 blocks in a single wave.
// ---------------------------------------------------------------------------
__global__ void __launch_bounds__(512, 3) rank_kernel(const float* __restrict__ x){
    extern __shared__ char sm[];
    unsigned*       du    = (unsigned*)sm;                  // 8192 u32
    unsigned*       hist  = du + 8192;                      // 4096 u32
    unsigned short* order = (unsigned short*)(hist + NBIN); // 8192 u16
    __shared__ unsigned wsum[32];

    const int col = blockIdx.x;
    const int tt  = col >> 3;
    const int e   = col & 7;
    const int tid = threadIdx.x;
    const float* xp = x + (size_t)(24 + tt) * F_DIM + e;

    // zero hist
    #pragma unroll
    for (int j = 0; j < NBIN/512; j++) hist[tid + j * 512] = 0u;

    // load values, write keys, count bins
    #pragma unroll
    for (int k = 0; k < 16; k++){
        int i = tid + k * 512;
        if (i < N_SAMP){
            float v = __ldg(xp + (size_t)i * (T_DIM * F_DIM));
            du[i] = desc_key(v);
            atomicAdd(&hist[bin_of_val(v)], 1u);
        } else {
            du[i] = 0xFFFFFFFFu;                            // padding
            atomicAdd(&hist[NBIN - 1], 1u);
        }
    }
    __syncthreads();

    // exclusive scan over 4096 bins: each thread owns 8 consecutive bins
    unsigned local[8];
    unsigned s = 0;
    const int b0 = tid * 8;
    #pragma unroll
    for (int j = 0; j < 8; j++){ local[j] = hist[b0 + j]; s += local[j]; }
    const unsigned lane = tid & 31, wid = tid >> 5;
    unsigned inc = s;
    #pragma unroll
    for (int off = 1; off < 32; off <<= 1){
        unsigned o = __shfl_up_sync(0xffffffffu, inc, off);
        if (lane >= off) inc += o;
    }
    if (lane == 31) wsum[wid] = inc;
    __syncthreads();
    if (wid == 0){
        unsigned vv = (lane < 16) ? wsum[lane] : 0u;        // 16 warps only
        unsigned ii = vv;
        #pragma unroll
        for (int off = 1; off < 32; off <<= 1){
            unsigned o = __shfl_up_sync(0xffffffffu, ii, off);
            if (lane >= off) ii += o;
        }
        wsum[lane] = ii - vv;                               // exclusive warp prefix
    }
    __syncthreads();
    unsigned run = wsum[wid] + (inc - s);                   // exclusive thread prefix
    #pragma unroll
    for (int j = 0; j < 8; j++){ unsigned c = local[j]; hist[b0 + j] = run; run += c; }
    __syncthreads();

    // scatter: atomic bump turns hist[b] from start into end
    #pragma unroll
    for (int k = 0; k < 16; k++){
        int i = tid + k * 512;
        unsigned kk = du[i];
        int b = (i < N_SAMP) ? bin_of_val(val_of_key(kk)) : (NBIN - 1);
        unsigned p = atomicAdd(&hist[b], 1u);
        order[p] = (unsigned short)i;
    }
    __syncthreads();

    // exact rank: base = #elements in smaller bins (all strictly larger values),
    // + within-bin count with (value, index) tie-break => stable argsort of -x.
    #pragma unroll
    for (int k = 0; k < 16; k++){
        int i = tid + k * 512;
        if (i < N_SAMP){
            unsigned kk = du[i];
            int b = bin_of_val(val_of_key(kk));
            unsigned start = b ? hist[b - 1] : 0u;          // end of b-1 == start of b
            unsigned end   = hist[b];
            int cnt = 0;
            for (unsigned q = start; q < end; q++){
                int m = order[q];
                unsigned km = du[m];
                cnt += (km < kk) || (km == kk && m < i);
            }
            g_rank[(size_t)i * NCOL + col] = (float)((int)start + cnt) * (1.0f / 8000.0f);
        }
    }
}

// ---------------------------------------------------------------------------
// Kernel 2: fused window-stats + single-channel conv + leaky-relu + linear.
// 320 threads / 8 samples per block: thread = (sample s, time t).
// (unchanged from the round-9 passing version: 58.6us)
// ---------------------------------------------------------------------------
__device__ __forceinline__ void ffma2(unsigned long long &d, unsigned long long a, unsigned long long b){
    asm("fma.rn.f32x2 %0, %1, %2, %0;" : "+l"(d) : "l"(a), "l"(b));
}
__device__ __forceinline__ float2 upk2(unsigned long long v){
    float2 f; asm("mov.b64 {%0, %1}, %2;" : "=f"(f.x), "=f"(f.y) : "l"(v)); return f;
}

__global__ void __launch_bounds__(320, 2) main_kernel(
    const float* __restrict__ x, const float* __restrict__ conv_w,
    const float* __restrict__ conv_b, const float* __restrict__ lin_w,
    const float* __restrict__ lin_b, float* __restrict__ out)
{
    extern __shared__ char sm[];
    float* xrowAll = (float*)sm;              // 8 * 40 * 68 = 21760 floats
    float* xeAll   = xrowAll + 8 * 40 * 68;   // 8 * 64 * 8  = 4096
    float* dAll    = xeAll   + 8 * 64 * 8;    // 8 * 200     = 1600
    float* wTs     = dAll    + 8 * 200;       // 720  (wTs[k*144 + c])
    float* linWs   = wTs + 720;               // 36
    float* miscS   = linWs + 36;              // 2

    const int tid   = threadIdx.x;
    const int nbase = blockIdx.x * 8;

    // transpose the single live conv filter: wTs[k][c] = conv_w[127][c][k]
    for (int idx = tid; idx < 720; idx += 320){
        int k = idx / 144, c = idx - k * 144;
        wTs[idx] = conv_w[W127 + c * 5 + k];
    }
    if (tid < 36) linWs[tid] = lin_w[tid];
    if (tid == 36) miscS[0] = conv_b[127];
    if (tid == 37) miscS[1] = lin_b[0];

    // stage rows 24..63, all 64 channels, 8 samples (coalesced, padded stride 68)
    #pragma unroll
    for (int s8 = 0; s8 < 8; s8++){
        const float* src = x + (size_t)(nbase + s8) * (T_DIM * F_DIM) + 1536;
        float* dst = xrowAll + s8 * 2720;
        #pragma unroll
        for (int it = 0; it < 2; it++){
            int f4  = it * 320 + tid;
            int row = f4 >> 4, cc = (f4 & 15) * 4;
            *(float4*)(dst + row * 68 + cc) = *(const float4*)(src + f4 * 4);
        }
    }
    // stage rows 0..63, first 8 features, 8 samples (for window stats)
    #pragma unroll
    for (int it = 0; it < 4; it++){
        int idx = it * 320 + tid;
        if (idx < 1024){
            int s = idx >> 7, q = idx & 127;
            int row = q >> 1, half = (q & 1) * 4;
            *(float4*)(xeAll + s * 512 + row * 8 + half) =
                *(const float4*)(x + (size_t)(nbase + s) * (T_DIM * F_DIM) + row * 64 + half);
        }
    }
    __syncthreads();

    const int s = tid / 40;                   // 0..7 (sample within block)
    const int t = tid - s * 40;               // 0..39
    const int n = nbase + s;
    const float4* xe4 = (const float4*)(xeAll + s * 512);
    float* dW = dAll + s * 200;

    float dst[5] = {0.f, 0.f, 0.f, 0.f, 0.f};
    auto acc4 = [&](int cb, float v0, float v1, float v2, float v3){
        #pragma unroll
        for (int k = 0; k < 5; k++){
            float4 wv = *(const float4*)(wTs + k * 144 + cb);
            dst[k] = fmaf(v0, wv.x, fmaf(v1, wv.y, fmaf(v2, wv.z, fmaf(v3, wv.w, dst[k]))));
        }
    };

    // ---- 20-window stats (rows 5+t .. 24+t), consumed immediately ----
    {
        float s20[8], q20[8], mx20[8], mn20[8];
        #pragma unroll
        for (int e2 = 0; e2 < 8; e2++){ s20[e2]=0.f; q20[e2]=0.f; mx20[e2]=-3.4e38f; mn20[e2]=3.4e38f; }
        #pragma unroll
        for (int j = 0; j < 20; j++){
            float4 a = xe4[(5 + t + j) * 2];
            float4 b = xe4[(5 + t + j) * 2 + 1];
            float v[8] = {a.x, a.y, a.z, a.w, b.x, b.y, b.z, b.w};
            #pragma unroll
            for (int e2 = 0; e2 < 8; e2++){
                float vv = v[e2];
                s20[e2] += vv;
                q20[e2]  = fmaf(vv, vv, q20[e2]);
                mx20[e2] = fmaxf(mx20[e2], vv);
                mn20[e2] = fminf(mn20[e2], vv);
            }
        }
        float mean20[8], std20[8];
        #pragma unroll
        for (int e2 = 0; e2 < 8; e2++){
            mean20[e2] = s20[e2] * 0.05f;
            std20[e2]  = sqrtf(fmaxf((q20[e2] - s20[e2]*s20[e2]*0.05f) * (1.0f/19.0f), 0.f));
        }
        acc4(104, mean20[0], mean20[1], mean20[2], mean20[3]);
        acc4(108, mean20[4], mean20[5], mean20[6], mean20[7]);
        acc4(112, std20[0], std20[1], std20[2], std20[3]);
        acc4(116, std20[4], std20[5], std20[6], std20[7]);
        acc4(128, mx20[0], mx20[1], mx20[2], mx20[3]);
        acc4(132, mx20[4], mx20[5], mx20[6], mx20[7]);
        acc4(136, mn20[0], mn20[1], mn20[2], mn20[3]);
        acc4(140, mn20[4], mn20[5], mn20[6], mn20[7]);
    }
    // ---- 5-window stats (rows 20+t .. 24+t), consumed immediately ----
    {
        float s5[8], q5[8], mx5[8], mn5[8];
        #pragma unroll
        for (int e2 = 0; e2 < 8; e2++){ s5[e2]=0.f; q5[e2]=0.f; mx5[e2]=-3.4e38f; mn5[e2]=3.4e38f; }
        #pragma unroll
        for (int j = 0; j < 5; j++){
            float4 a = xe4[(20 + t + j) * 2];
            float4 b = xe4[(20 + t + j) * 2 + 1];
            float v[8] = {a.x, a.y, a.z, a.w, b.x, b.y, b.z, b.w};
            #pragma unroll
            for (int e2 = 0; e2 < 8; e2++){
                float vv = v[e2];
                s5[e2] += vv;
                q5[e2]  = fmaf(vv, vv, q5[e2]);
                mx5[e2] = fmaxf(mx5[e2], vv);
                mn5[e2] = fminf(mn5[e2], vv);
            }
        }
        float mean5[8], std5[8];
        #pragma unroll
        for (int e2 = 0; e2 < 8; e2++){
            mean5[e2] = s5[e2] * 0.2f;
            std5[e2]  = sqrtf(fmaxf((q5[e2] - s5[e2]*s5[e2]*0.2f) * 0.25f, 0.f));
        }
        acc4( 64, mean5[0], mean5[1], mean5[2], mean5[3]);
        acc4( 68, mean5[4], mean5[5], mean5[6], mean5[7]);
        acc4( 72, std5[0], std5[1], std5[2], std5[3]);
        acc4( 76, std5[4], std5[5], std5[6], std5[7]);
        acc4( 88, mx5[0], mx5[1], mx5[2], mx5[3]);
        acc4( 92, mx5[4], mx5[5], mx5[6], mx5[7]);
        acc4( 96, mn5[0], mn5[1], mn5[2], mn5[3]);
        acc4(100, mn5[4], mn5[5], mn5[6], mn5[7]);
    }
    // ---- ranks (identical for week & month channel groups) ----
    {
        const float4* rp = (const float4*)(g_rank + (size_t)n * NCOL + t * 8);
        float4 rka = rp[0], rkb = rp[1];
        acc4( 80, rka.x, rka.y, rka.z, rka.w);
        acc4( 84, rkb.x, rkb.y, rkb.z, rkb.w);
        acc4(120, rka.x, rka.y, rka.z, rka.w);
        acc4(124, rkb.x, rkb.y, rkb.z, rkb.w);
    }
    // ---- raw 64-channel dot via packed f32x2 FMA ----
    {
        unsigned long long dax[5], day[5];
        #pragma unroll
        for (int k = 0; k < 5; k++){ dax[k] = 0ULL; day[k] = 0ULL; }
        const ulonglong2* xr2 = (const ulonglong2*)(xrowAll + s * 2720 + t * 68);
        #pragma unroll
        for (int c4 = 0; c4 < 16; c4++){
            ulonglong2 xv = xr2[c4];
            #pragma unroll
            for (int k = 0; k < 5; k++){
                ulonglong2 wv = *(const ulonglong2*)(wTs + k * 144 + c4 * 4);
                ffma2(dax[k], xv.x, wv.x);
                ffma2(day[k], xv.y, wv.y);
            }
        }
        #pragma unroll
        for (int k = 0; k < 5; k++){
            float2 a1 = upk2(dax[k]), a2 = upk2(day[k]);
            dW[t * 5 + k] = dst[k] + ((a1.x + a1.y) + (a2.x + a2.y));
        }
    }
    __syncthreads();

    // conv taps across t + bias + leaky relu + linear head: warp per sample.
    // 36 positions on 32 lanes: lane p handles position p; lanes 0..3 also
    // handle positions 32..35.
    const int lane = tid & 31, w = tid >> 5;
    if (w < 8){
        const float* dWw = dAll + w * 200;
        const float convB = miscS[0], linB = miscS[1];
        float h = convB;
        #pragma unroll
        for (int k = 0; k < 5; k++) h += dWw[(lane + k) * 5 + k];
        h = (h >= 0.f) ? h : 0.01f * h;
        float c = h * linWs[lane];
        if (lane < 4){
            float h2 = convB;
            #pragma unroll
            for (int k = 0; k < 5; k++) h2 += dWw[(lane + 32 + k) * 5 + k];
            h2 = (h2 >= 0.f) ? h2 : 0.01f * h2;
            c = fmaf(h2, linWs[lane + 32], c);
        }
        #pragma unroll
        for (int off = 16; off; off >>= 1) c += __shfl_down_sync(0xffffffffu, c, off);
        if (lane == 0) out[nbase + w] = c + linB;
    }
}

// ---------------------------------------------------------------------------
extern "C" void kernel_launch(void* const* d_in, const int* in_sizes, int n_in,
                              void* d_out, int out_size)
{
    const float* x      = (const float*)d_in[0];
    const float* conv_w = (const float*)d_in[1];
    const float* conv_b = (const float*)d_in[2];
    const float* lin_w  = (const float*)d_in[3];
    const float* lin_b  = (const float*)d_in[4];
    float* out = (float*)d_out;

    cudaFuncSetAttribute(rank_kernel, cudaFuncAttributeMaxDynamicSharedMemorySize, 65536);
    cudaFuncSetAttribute(main_kernel, cudaFuncAttributeMaxDynamicSharedMemorySize, 112896);

    rank_kernel<<<NCOL, 512, 65536>>>(x);
    main_kernel<<<N_SAMP / 8, 320, 112896>>>(x, conv_w, conv_b, lin_w, lin_b, out);
}